// round 12
// baseline (speedup 1.0000x reference)
#include <cuda_runtime.h>
#include <math.h>

#define MAX_DIM 2048
#define GTHREADS 256

// ---------------- Fast path: nq=11, real-only output, 4 amps/thread.
// out = WHT( WHT(s) ⊙ cosφ ) / 2048  (real arithmetic; Rx = H·Rz·H).
// 512 threads per CTA, ONE vector per CTA -> 256 CTAs, 16 warps/CTA
// (double the resident warps of the 256-thread variant). Amp bits:
//   0..1 regs (j), 2..6 lanes (l), 7..10 warps (w = wh:wl).
// Two 2-bit smem permutes move warp bits into regs; the
// "write-exactly-what-you-read" ordering keeps it at 4 barriers total.
#define FDIM   2048
#define FNQ    11
#define FTHREADS 512
#define SPAD(n) ((n) + ((n) >> 5))

__global__ __launch_bounds__(FTHREADS, 2)
void rx_wht4_kernel(const float* __restrict__ state,
                    const float* __restrict__ weights,
                    float* __restrict__ out,
                    int nvec, int nblocks)
{
    __shared__ float s_a[SPAD(FDIM - 1) + 1];
    __shared__ float T26c[32], T26s[32];  // amp bits 2..6  (qubits 8..4)
    __shared__ float T01c[4],  T01s[4];   // amp bits 0..1  (qubits 10,9)
    __shared__ float T78c[4],  T78s[4];   // amp bits 7..8  (qubits 3,2)
    __shared__ float T9Ac[4],  T9As[4];   // amp bits 9..10 (qubits 1,0), /2048 folded

    const int tl = threadIdx.x;           // 9 bits
    const int w  = tl >> 5;               // 4 bits (amp bits 7..10)
    const int l  = tl & 31;               // 5 bits (amp bits 2..6)
    const int wh = w >> 2;                // amp bits 9..10
    const int wl = w & 3;                 // amp bits 7..8
    const int vec = blockIdx.x;
    const int bl  = vec % nblocks;
    const float* W = weights + bl * FNQ;

    float x[4];

    // Coalesced load: thread tl owns amps [4tl, 4tl+4)
    {
        const float4 v = ((const float4*)(state + (size_t)vec * FDIM))[tl];
        x[0] = v.x; x[1] = v.y; x[2] = v.z; x[3] = v.w;
    }

    // Phase tables (amp bit b hosts qubit 10-b; + if bit set else -).
    if (tl < 32) {
        float p = 0.0f;
        #pragma unroll
        for (int k = 0; k < 5; k++)
            p += ((tl >> k) & 1) ? 0.5f * W[8 - k] : -0.5f * W[8 - k];
        float s, c; __sincosf(p, &s, &c);
        T26c[tl] = c; T26s[tl] = s;
    } else if (tl < 44) {
        const int g = (tl - 32) >> 2;     // 0,1,2
        const int i = (tl - 32) & 3;
        float p;
        if (g == 0) {        // bits 0..1 -> qubits 10, 9
            p = ((i & 1) ? 0.5f : -0.5f) * W[10] + ((i >> 1) ? 0.5f : -0.5f) * W[9];
            float s, c; __sincosf(p, &s, &c);
            T01c[i] = c; T01s[i] = s;
        } else if (g == 1) { // bits 7..8 -> qubits 3, 2
            p = ((i & 1) ? 0.5f : -0.5f) * W[3] + ((i >> 1) ? 0.5f : -0.5f) * W[2];
            float s, c; __sincosf(p, &s, &c);
            T78c[i] = c; T78s[i] = s;
        } else {             // bits 9..10 -> qubits 1, 0
            p = ((i & 1) ? 0.5f : -0.5f) * W[1] + ((i >> 1) ? 0.5f : -0.5f) * W[0];
            float s, c; __sincosf(p, &s, &c);
            T9Ac[i] = c * (1.0f / 2048.0f);
            T9As[i] = s * (1.0f / 2048.0f);
        }
    }

    // Address maps (bijections over the 11 amp bits):
    //  n(j) = (w<<7)|(l<<2)|j            regs = amp bits 0..1
    //  m(j) = (wh<<9)|(j<<7)|(l<<2)|wl   regs = amp bits 7..8
    //  p(j) = (j<<9)|(wh<<7)|(l<<2)|wl   regs = amp bits 9..10
    const int nb = (w << 7) | (l << 2);
    const int mb = (wh << 9) | (l << 2) | wl;
    const int pb = (wh << 7) | (l << 2) | wl;

    // ---- forward WHT: reg bits 0..1
    { const float a0 = x[0], a1 = x[1], a2 = x[2], a3 = x[3];
      const float b0 = a0 + a1, b1 = a0 - a1, b2 = a2 + a3, b3 = a2 - a3;
      x[0] = b0 + b2; x[1] = b1 + b3; x[2] = b0 - b2; x[3] = b1 - b3; }
    // ---- forward WHT: lane bits (amp bits 2..6)
    #pragma unroll
    for (int k = 0; k < 5; k++) {
        const float sgn = ((l >> k) & 1) ? -1.0f : 1.0f;
        #pragma unroll
        for (int j = 0; j < 4; j++) {
            const float p = __shfl_xor_sync(0xffffffffu, x[j], 1 << k);
            x[j] = fmaf(sgn, x[j], p);
        }
    }
    // ---- permute 1: regs <- amp bits 7..8
    #pragma unroll
    for (int j = 0; j < 4; j++) s_a[SPAD(nb | j)] = x[j];
    __syncthreads();                      // bar1 (also publishes tables)
    #pragma unroll
    for (int j = 0; j < 4; j++) x[j] = s_a[SPAD(mb | (j << 7))];
    // ---- forward WHT: amp bits 7..8
    { const float a0 = x[0], a1 = x[1], a2 = x[2], a3 = x[3];
      const float b0 = a0 + a1, b1 = a0 - a1, b2 = a2 + a3, b3 = a2 - a3;
      x[0] = b0 + b2; x[1] = b1 + b3; x[2] = b0 - b2; x[3] = b1 - b3; }
    // ---- permute 2: regs <- amp bits 9..10 (write own just-read slots)
    #pragma unroll
    for (int j = 0; j < 4; j++) s_a[SPAD(mb | (j << 7))] = x[j];
    __syncthreads();                      // bar2
    #pragma unroll
    for (int j = 0; j < 4; j++) x[j] = s_a[SPAD(pb | (j << 9))];
    // ---- forward WHT: amp bits 9..10
    { const float a0 = x[0], a1 = x[1], a2 = x[2], a3 = x[3];
      const float b0 = a0 + a1, b1 = a0 - a1, b2 = a2 + a3, b3 = a2 - a3;
      x[0] = b0 + b2; x[1] = b1 + b3; x[2] = b0 - b2; x[3] = b1 - b3; }

    // ---- diagonal: fixed bits 0..1=wl, 2..6=l, 7..8=wh; reg bits 9..10=j
    {
        const float c0 = T01c[wl], s0 = T01s[wl];
        const float cl = T26c[l],  sl = T26s[l];
        float c1 = fmaf(c0, cl, -s0 * sl);
        float s1 = fmaf(s0, cl,  c0 * sl);
        const float cw = T78c[wh], sw = T78s[wh];
        const float cf = fmaf(c1, cw, -s1 * sw);
        const float sf = fmaf(s1, cw,  c1 * sw);
        #pragma unroll
        for (int j = 0; j < 4; j++)
            x[j] *= fmaf(cf, T9Ac[j], -sf * T9As[j]);
    }

    // ---- inverse WHT: amp bits 9..10
    { const float a0 = x[0], a1 = x[1], a2 = x[2], a3 = x[3];
      const float b0 = a0 + a1, b1 = a0 - a1, b2 = a2 + a3, b3 = a2 - a3;
      x[0] = b0 + b2; x[1] = b1 + b3; x[2] = b0 - b2; x[3] = b1 - b3; }
    // ---- permute back: regs <- amp bits 7..8
    #pragma unroll
    for (int j = 0; j < 4; j++) s_a[SPAD(pb | (j << 9))] = x[j];
    __syncthreads();                      // bar3
    #pragma unroll
    for (int j = 0; j < 4; j++) x[j] = s_a[SPAD(mb | (j << 7))];
    // ---- inverse WHT: amp bits 7..8
    { const float a0 = x[0], a1 = x[1], a2 = x[2], a3 = x[3];
      const float b0 = a0 + a1, b1 = a0 - a1, b2 = a2 + a3, b3 = a2 - a3;
      x[0] = b0 + b2; x[1] = b1 + b3; x[2] = b0 - b2; x[3] = b1 - b3; }
    // ---- permute back: regs <- amp bits 0..1
    #pragma unroll
    for (int j = 0; j < 4; j++) s_a[SPAD(mb | (j << 7))] = x[j];
    __syncthreads();                      // bar4
    #pragma unroll
    for (int j = 0; j < 4; j++) x[j] = s_a[SPAD(nb | j)];
    // ---- inverse WHT: lane bits 2..6
    #pragma unroll
    for (int k = 0; k < 5; k++) {
        const float sgn = ((l >> k) & 1) ? -1.0f : 1.0f;
        #pragma unroll
        for (int j = 0; j < 4; j++) {
            const float p = __shfl_xor_sync(0xffffffffu, x[j], 1 << k);
            x[j] = fmaf(sgn, x[j], p);
        }
    }
    // ---- inverse WHT: reg bits 0..1
    { const float a0 = x[0], a1 = x[1], a2 = x[2], a3 = x[3];
      const float b0 = a0 + a1, b1 = a0 - a1, b2 = a2 + a3, b3 = a2 - a3;
      x[0] = b0 + b2; x[1] = b1 + b3; x[2] = b0 - b2; x[3] = b1 - b3; }

    // ---- coalesced real-only store
    ((float4*)out)[(size_t)vec * (FDIM / 4) + tl] =
        make_float4(x[0], x[1], x[2], x[3]);
}

// ---------------- Generic fallback (proven R7 kernel, fully guarded).
__global__ __launch_bounds__(GTHREADS)
void rx_layer_kernel(const float* __restrict__ state,
                     const float* __restrict__ weights,
                     float* __restrict__ out,
                     int nvec, int nblocks, int nq, int dim,
                     long stateLimF, long wLimF, long outCapF,
                     int interleaved)
{
    __shared__ __align__(16) float2 amp[MAX_DIM];
    __shared__ float sa[32];
    __shared__ float sb[32];

    const int tid = threadIdx.x;

    for (int vec = blockIdx.x; vec < nvec; vec += gridDim.x) {
        const int bl = vec % nblocks;
        const long sbase = (long)vec * dim;
        for (int i = tid; i < dim; i += GTHREADS) {
            const long gi = sbase + i;
            amp[i] = make_float2((gi < stateLimF) ? state[gi] : 0.0f, 0.0f);
        }
        if (tid < nq) {
            const long widx = (long)bl * nq + tid;
            const float wv = (widx < wLimF) ? weights[widx] : 0.0f;
            float s, c;
            sincosf(wv * 0.5f, &s, &c);
            sa[tid] = c;
            sb[tid] = s;
        }
        __syncthreads();
        for (int q = 0; q < nq; q++) {
            const int   st   = 1 << (nq - 1 - q);
            const float a    = sa[q];
            const float b    = sb[q];
            const int   half = dim >> 1;
            for (int p = tid; p < half; p += GTHREADS) {
                const int lo = ((p & ~(st - 1)) << 1) | (p & (st - 1));
                const int hi = lo + st;
                const float2 xx = amp[lo];
                const float2 yy = amp[hi];
                amp[lo] = make_float2(fmaf(a, xx.x,  b * yy.y),
                                      fmaf(a, xx.y, -b * yy.x));
                amp[hi] = make_float2(fmaf(a, yy.x,  b * xx.y),
                                      fmaf(a, yy.y, -b * xx.x));
            }
            __syncthreads();
        }
        if (interleaved) {
            const long obase = 2L * (long)vec * dim;
            for (int i = tid; i < dim; i += GTHREADS) {
                const long fo = obase + 2L * i;
                if (fo + 1 < outCapF) {
                    out[fo]     = amp[i].x;
                    out[fo + 1] = amp[i].y;
                }
            }
        } else {
            const long obase = (long)vec * dim;
            for (int i = tid; i < dim; i += GTHREADS) {
                const long fo = obase + i;
                if (fo < outCapF) out[fo] = amp[i].x;
            }
        }
        __syncthreads();
    }
}

extern "C" void kernel_launch(void* const* d_in, const int* in_sizes, int n_in,
                              void* d_out, int out_size)
{
    int si = 0;
    for (int i = 1; i < n_in; i++) if (in_sizes[i] > in_sizes[si]) si = i;
    int wi = (si == 0) ? ((n_in > 1) ? 1 : 0) : 0;

    const float* state   = (const float*)d_in[si];
    const float* weights = (const float*)d_in[wi];
    const long stateE = in_sizes[si];
    const long wE     = in_sizes[wi];

    int nq = -1, dim = 0, nvec = 0, nblocks = 1;
    for (int q = 1; q <= 20; q++) {
        if (wE <= 0 || wE % q) continue;
        const long d = 1L << q;
        if (d > MAX_DIM || stateE % d) continue;
        const long nv = stateE / d;
        const long nb = wE / q;
        if (nb <= 0 || nv % nb) continue;
        nq = q; dim = (int)d; nvec = (int)nv; nblocks = (int)nb;
    }
    if (nq < 0) { nq = 1; dim = 2; nvec = (int)(stateE >= 2 ? stateE / 2 : 1); nblocks = 1; }

    const long outCapF = out_size;   // floats: minimal safe interpretation
    const int interleaved = (outCapF >= 2L * (long)nvec * dim) ? 1 : 0;

    const bool fast = (nq == FNQ) && (dim == FDIM) && nvec >= 1 &&
                      (stateE == (long)nvec * FDIM) &&
                      (wE == (long)nblocks * FNQ) &&
                      !interleaved &&
                      (outCapF >= (long)nvec * FDIM);

    if (fast) {
        rx_wht4_kernel<<<nvec, FTHREADS>>>(state, weights, (float*)d_out,
                                           nvec, nblocks);
    } else {
        int grid = nvec < 2048 ? nvec : 2048;
        if (grid < 1) grid = 1;
        rx_layer_kernel<<<grid, GTHREADS>>>(state, weights, (float*)d_out,
                                            nvec, nblocks, nq, dim,
                                            stateE, wE, outCapF, interleaved);
    }
}